// round 8
// baseline (speedup 1.0000x reference)
#include <cuda_runtime.h>
#include <cuda_fp16.h>
#include <math.h>
#include <stdint.h>

#define NTOK  65536
#define IN_F  64
#define OUT_F 64
#define RAD_F 32
#define ANG_F 16
#define HID   64

#define TILE_M   128
#define NTILES   (NTOK / TILE_M)   // 512
#define THREADS  256

#define APITCH   144               // padded row: 64 fp16 = 128B + 16B pad
#define B_SLOT   9216              // 64 rows * 144 B
#define STAGE    (2 * B_SLOT)      // 2 i-slots per pipeline stage

// ---------------------------------------------------------------------------
// Device-global scratch (weights only)
// ---------------------------------------------------------------------------
__device__ __align__(1024) uint8_t g_W2t[(size_t)64 * B_SLOT];  // B_i[o][k] fp16
__device__ __align__(1024) uint8_t g_b2t[B_SLOT];               // b2 [o][i] fp16

__global__ void tp_wsplit(const float* __restrict__ W2, const float* __restrict__ b2)
{
    const int idx = blockIdx.x * THREADS + threadIdx.x;
    if (idx < 64 * 4096) {
        const int k  = idx >> 12;
        const int io = idx & 4095;
        const int o  = io & 63;
        const int i  = io >> 6;
        *(__half*)(g_W2t + (size_t)i * B_SLOT + o * APITCH + k * 2) =
            __float2half_rn(W2[idx]);
    } else if (idx < 64 * 4096 + 4096) {
        const int e = idx - 64 * 4096;
        const int i = e >> 6;
        const int o = e & 63;
        *(__half*)(g_b2t + o * APITCH + i * 2) = __float2half_rn(b2[e]);
    }
}

// ---------------------------------------------------------------------------
// PTX helpers (baseline sm_80+)
// ---------------------------------------------------------------------------
__device__ __forceinline__ void cp16(uint32_t s, const void* g) {
    asm volatile("cp.async.cg.shared.global [%0], [%1], 16;" :: "r"(s), "l"(g));
}
__device__ __forceinline__ void ldsm_x4(uint32_t* r, uint32_t addr) {
    asm volatile("ldmatrix.sync.aligned.m8n8.x4.shared.b16 {%0,%1,%2,%3}, [%4];"
        : "=r"(r[0]), "=r"(r[1]), "=r"(r[2]), "=r"(r[3]) : "r"(addr));
}
__device__ __forceinline__ void mma_f16(float* d, const uint32_t* a,
                                        uint32_t b0, uint32_t b1) {
    asm volatile(
        "mma.sync.aligned.m16n8k16.row.col.f32.f16.f16.f32 "
        "{%0,%1,%2,%3}, {%4,%5,%6,%7}, {%8,%9}, {%0,%1,%2,%3};"
        : "+f"(d[0]), "+f"(d[1]), "+f"(d[2]), "+f"(d[3])
        : "r"(a[0]), "r"(a[1]), "r"(a[2]), "r"(a[3]), "r"(b0), "r"(b1));
}
__device__ __forceinline__ uint32_t hmul2u(uint32_t a, uint32_t f) {
    uint32_t d;
    asm("mul.rn.f16x2 %0, %1, %2;" : "=r"(d) : "r"(a), "r"(f));
    return d;
}
__device__ __forceinline__ uint32_t hdup(uint32_t smem_addr) {
    uint32_t h;
    asm volatile("ld.shared.u16 %0, [%1];" : "=r"(h) : "r"(smem_addr));
    return h | (h << 16);
}

// ---------------------------------------------------------------------------
// SMEM layout (bytes)  — TILE_M = 128
// ---------------------------------------------------------------------------
#define SM_A    0u        // h fp16 tile 128 rows     (18432)
#define SM_F    18432u    // f fp16 tile 128 rows     (18432)
#define SM_B    36864u    // 4 stages x 18432         (73728)
#define SM_B2   110592u   // b2 tile                  (9216)
#define SM_RAD  119808u   // radial fp32 [128][32]    (16384)
#define SM_ANG  136192u   // angular fp32 [128][17]   (8704)
#define SM_W1   144896u   // W1 fp32 [32][64]         (8192)
#define SM_WA   153088u   // Wa fp32 [16][64]         (4096)
#define SM_B1   157184u   // b1 fp32 [64]             (256)
#define SM_BA   157440u   // ba fp32 [64]             (256)
#define SMEM_BYTES 157696

// ---------------------------------------------------------------------------
// Fused main kernel: 128 tokens/CTA, 8 warps.
// Warp = (m-pair, n-half): 32 rows (2 m16 bands) x 32 output cols (4 n8 tiles)
// ---------------------------------------------------------------------------
__global__ __launch_bounds__(THREADS, 1)
void tp_main(const float* __restrict__ features,
             const float* __restrict__ radial,
             const float* __restrict__ angular,
             const float* __restrict__ W1,
             const float* __restrict__ b1,
             const float* __restrict__ Wa,
             const float* __restrict__ ba,
             float* __restrict__ out)
{
    extern __shared__ __align__(1024) uint8_t smem[];
    const uint32_t sb = (uint32_t)__cvta_generic_to_shared(smem);
    const int tid  = threadIdx.x;
    const int lane = tid & 31;
    const int warp = tid >> 5;
    const int n0   = blockIdx.x * TILE_M;

    // ---- cp.async groups: g0..g2 = B stages 0..2, g3 = b2 tile ----
#pragma unroll
    for (int s = 0; s < 3; s++) {
        const uint8_t* src = g_W2t + (size_t)s * STAGE;
        for (int e = tid; e < 1152; e += THREADS)
            cp16(sb + SM_B + s * STAGE + e * 16, src + e * 16);
        asm volatile("cp.async.commit_group;");
    }
    for (int e = tid; e < 576; e += THREADS) cp16(sb + SM_B2 + e * 16, g_b2t + e * 16);
    asm volatile("cp.async.commit_group;");

    // ---- stage inputs (overlaps cp.async) ----
    float* srad = (float*)(smem + SM_RAD);   // [128][32]
    float* sang = (float*)(smem + SM_ANG);   // [128][17]
    float* sW1  = (float*)(smem + SM_W1);
    float* sWa  = (float*)(smem + SM_WA);
    float* sb1_ = (float*)(smem + SM_B1);
    float* sba_ = (float*)(smem + SM_BA);

    for (int e = tid; e < TILE_M * IN_F; e += THREADS) {
        const int m = e >> 6, c = e & 63;
        const float v = features[(size_t)(n0 + m) * IN_F + c];
        *(__half*)(smem + SM_F + m * APITCH + c * 2) = __float2half_rn(v);
    }
    for (int e = tid; e < TILE_M * RAD_F; e += THREADS) {
        const int m = e >> 5, r = e & 31;
        srad[m * 32 + r] = radial[(size_t)(n0 + m) * RAD_F + r];
    }
    for (int e = tid; e < TILE_M * ANG_F; e += THREADS) {
        const int m = e >> 4, r = e & 15;
        sang[m * 17 + r] = angular[(size_t)(n0 + m) * ANG_F + r];
    }
    for (int e = tid; e < RAD_F * HID; e += THREADS) sW1[e] = W1[e];
    for (int e = tid; e < ANG_F * OUT_F; e += THREADS) sWa[e] = Wa[e];
    if (tid < HID)   sb1_[tid] = b1[tid];
    else if (tid < HID + OUT_F) sba_[tid - HID] = ba[tid - HID];
    __syncthreads();

    // ---- h = silu(radial@W1+b1) -> A tile (fp16) ----
    {
        const int j  = tid & 63;
        const int mb = tid >> 6;
#pragma unroll 4
        for (int s = 0; s < TILE_M / 4; s++) {
            const int m = mb + s * 4;
            float a = sb1_[j];
#pragma unroll
            for (int r = 0; r < RAD_F; r++)
                a = fmaf(srad[m * 32 + r], sW1[r * HID + j], a);
            const float hv = a / (1.0f + expf(-a));
            *(__half*)(smem + SM_A + m * APITCH + j * 2) = __float2half_rn(hv);
        }
    }
    __syncthreads();

    // ---- warp decomposition ----
    const int mpair = warp >> 1;          // 0..3 -> rows mpair*32 .. +31
    const int nhalf = warp & 1;           // 0..1 -> cols nhalf*32 .. +31
    const int m0    = mpair * 32;
    const int nc0   = nhalf * 32;

    const uint32_t a_row  = ((lane >> 3) & 1) * 8 + (lane & 7);
    const uint32_t a_kadd = (lane >> 4) * 16;
    const uint32_t b_row  = ((lane >> 4) & 1) * 8 + (lane & 7);
    const uint32_t b_kadd = ((lane >> 3) & 1) * 16;
    const int r0 = lane >> 2;

    // ---- preload raw A fragments for both bands ----
    uint32_t Ah0[4][4], Ah1[4][4];
    {
        const uint32_t base0 = sb + SM_A + (m0 + a_row) * APITCH + a_kadd;
        const uint32_t base1 = base0 + 16 * APITCH;
#pragma unroll
        for (int ks = 0; ks < 4; ks++) ldsm_x4(Ah0[ks], base0 + ks * 32);
#pragma unroll
        for (int ks = 0; ks < 4; ks++) ldsm_x4(Ah1[ks], base1 + ks * 32);
    }

    float acc0[4][4], acc1[4][4];
#pragma unroll
    for (int nt = 0; nt < 4; nt++)
#pragma unroll
        for (int j = 0; j < 4; j++) { acc0[nt][j] = 0.0f; acc1[nt][j] = 0.0f; }

    // f fp16 smem addresses for this thread's 4 rows
    const uint32_t fa0 = sb + SM_F + (m0 + r0) * APITCH;       // band0 row r0
    const uint32_t fa1 = fa0 + 8 * APITCH;                     // band0 row r0+8
    const uint32_t fa2 = fa0 + 16 * APITCH;                    // band1 row r0
    const uint32_t fa3 = fa0 + 24 * APITCH;                    // band1 row r0+8

    // B row offset for this warp's 32-col half
    const uint32_t brow_off = (nc0 + b_row) * APITCH + b_kadd;

    // ---- 32 iterations x 2 i-slots; 4-stage pipeline, 1 sync/iter ----
    for (int j = 0; j < 32; j++) {
        if (j < 30)       asm volatile("cp.async.wait_group 2;");
        else if (j == 30) asm volatile("cp.async.wait_group 1;");
        else              asm volatile("cp.async.wait_group 0;");
        __syncthreads();

        const uint32_t bbase = sb + SM_B + (j & 3) * STAGE;

#pragma unroll
        for (int half = 0; half < 2; half++) {
            const int i = 2 * j + half;
            const uint32_t sbb = bbase + half * B_SLOT + brow_off;

            const uint32_t f0 = hdup(fa0 + i * 2);
            const uint32_t f1 = hdup(fa1 + i * 2);
            const uint32_t f2 = hdup(fa2 + i * 2);
            const uint32_t f3 = hdup(fa3 + i * 2);

#pragma unroll
            for (int ks = 0; ks < 4; ks++) {
                uint32_t bh[8];
                ldsm_x4(bh,     sbb + ks * 32);
                ldsm_x4(bh + 4, sbb + 16 * APITCH + ks * 32);

                // A frag regs {0,2} = row r0, {1,3} = row r0+8
                uint32_t As0[4], As1[4];
                As0[0] = hmul2u(Ah0[ks][0], f0);
                As0[1] = hmul2u(Ah0[ks][1], f1);
                As0[2] = hmul2u(Ah0[ks][2], f0);
                As0[3] = hmul2u(Ah0[ks][3], f1);
                As1[0] = hmul2u(Ah1[ks][0], f2);
                As1[1] = hmul2u(Ah1[ks][1], f3);
                As1[2] = hmul2u(Ah1[ks][2], f2);
                As1[3] = hmul2u(Ah1[ks][3], f3);

#pragma unroll
                for (int nt = 0; nt < 4; nt++) {
                    const uint32_t b0  = bh[(nt >> 1) * 4 + (nt & 1) * 2];
                    const uint32_t b1v = bh[(nt >> 1) * 4 + (nt & 1) * 2 + 1];
                    mma_f16(acc0[nt], As0, b0, b1v);
                    mma_f16(acc1[nt], As1, b0, b1v);
                }
            }
        }

        if (j + 3 < 32) {
            const uint8_t* src = g_W2t + (size_t)(j + 3) * STAGE;
            const uint32_t dst = sb + SM_B + ((j + 3) & 3) * STAGE;
            for (int e = tid; e < 1152; e += THREADS)
                cp16(dst + e * 16, src + e * 16);
            asm volatile("cp.async.commit_group;");
        }
    }

    // ---- bias slot: acc += f @ b2 (unscaled F fragments) ----
    {
        const uint32_t base0 = sb + SM_F + (m0 + a_row) * APITCH + a_kadd;
        const uint32_t base1 = base0 + 16 * APITCH;
        const uint32_t b2b   = sb + SM_B2 + brow_off;
#pragma unroll
        for (int ks = 0; ks < 4; ks++) {
            uint32_t Fh0[4], Fh1[4], bh[8];
            ldsm_x4(Fh0, base0 + ks * 32);
            ldsm_x4(Fh1, base1 + ks * 32);
            ldsm_x4(bh,     b2b + ks * 32);
            ldsm_x4(bh + 4, b2b + 16 * APITCH + ks * 32);
#pragma unroll
            for (int nt = 0; nt < 4; nt++) {
                const uint32_t b0  = bh[(nt >> 1) * 4 + (nt & 1) * 2];
                const uint32_t b1v = bh[(nt >> 1) * 4 + (nt & 1) * 2 + 1];
                mma_f16(acc0[nt], Fh0, b0, b1v);
                mma_f16(acc1[nt], Fh1, b0, b1v);
            }
        }
    }

    // ---- epilogue: ang = angular@Wa+ba on the fly, multiply, store ----
    const int gc = (lane & 3) * 2;
#pragma unroll
    for (int band = 0; band < 2; band++) {
        float (*ac)[4] = band ? acc1 : acc0;
#pragma unroll
        for (int rs = 0; rs < 2; rs++) {    // D frag: {0,1}=row r0, {2,3}=row r0+8
            const int m = m0 + band * 16 + rs * 8 + r0;
            float sa[16];
#pragma unroll
            for (int q = 0; q < 16; q++) sa[q] = sang[m * 17 + q];

            const size_t orow = (size_t)(n0 + m) * OUT_F;
#pragma unroll
            for (int nt = 0; nt < 4; nt++) {
                const int c0 = nc0 + nt * 8 + gc;
                float a0 = sba_[c0], a1 = sba_[c0 + 1];
#pragma unroll
                for (int q = 0; q < 16; q++) {
                    a0 = fmaf(sa[q], sWa[q * 64 + c0], a0);
                    a1 = fmaf(sa[q], sWa[q * 64 + c0 + 1], a1);
                }
                float2 o;
                o.x = ac[nt][rs * 2 + 0] * a0;
                o.y = ac[nt][rs * 2 + 1] * a1;
                *(float2*)(out + orow + c0) = o;
            }
        }
    }
}

// ---------------------------------------------------------------------------
// Launch
// ---------------------------------------------------------------------------
extern "C" void kernel_launch(void* const* d_in, const int* in_sizes, int n_in,
                              void* d_out, int out_size)
{
    const float* features = (const float*)d_in[0];
    const float* radial   = (const float*)d_in[1];
    const float* angular  = (const float*)d_in[2];
    const float* W1       = (const float*)d_in[3];
    const float* b1       = (const float*)d_in[4];
    const float* W2       = (const float*)d_in[5];
    const float* b2       = (const float*)d_in[6];
    const float* Wa       = (const float*)d_in[7];
    const float* ba       = (const float*)d_in[8];
    float* out = (float*)d_out;
    (void)in_sizes; (void)n_in; (void)out_size;

    cudaFuncSetAttribute(tp_main, cudaFuncAttributeMaxDynamicSharedMemorySize, SMEM_BYTES);

    tp_wsplit<<<(64 * 4096 + 4096 + THREADS - 1) / THREADS, THREADS>>>(W2, b2);
    tp_main<<<NTILES, THREADS, SMEM_BYTES>>>(features, radial, angular,
                                             W1, b1, Wa, ba, out);
}

// round 9
// speedup vs baseline: 1.1306x; 1.1306x over previous
#include <cuda_runtime.h>
#include <cuda_fp16.h>
#include <math.h>
#include <stdint.h>

#define NTOK  65536
#define IN_F  64
#define OUT_F 64
#define RAD_F 32
#define ANG_F 16
#define HID   64

#define TILE_M   128
#define NTILES   (NTOK / TILE_M)   // 512
#define THREADS  256

#define APITCH   144               // padded row: 64 fp16 = 128B + 16B pad
#define B_SLOT   9216              // 64 rows * 144 B
#define STAGE    (2 * B_SLOT)      // 2 i-slots per pipeline stage
#define NSTAGE   3

// ---------------------------------------------------------------------------
// Device-global scratch: 66-slot weight stream (W2 slots 0..63, b2 at 64,
// slot 65 zero / never consumed)
// ---------------------------------------------------------------------------
__device__ __align__(1024) uint8_t g_stream[(size_t)66 * B_SLOT];

__global__ void tp_wsplit(const float* __restrict__ W2, const float* __restrict__ b2)
{
    const int idx = blockIdx.x * THREADS + threadIdx.x;
    if (idx < 64 * 4096) {
        const int k  = idx >> 12;
        const int io = idx & 4095;
        const int o  = io & 63;
        const int i  = io >> 6;
        *(__half*)(g_stream + (size_t)i * B_SLOT + o * APITCH + k * 2) =
            __float2half_rn(W2[idx]);
    } else if (idx < 64 * 4096 + 4096) {
        const int e = idx - 64 * 4096;
        const int i = e >> 6;
        const int o = e & 63;
        *(__half*)(g_stream + (size_t)64 * B_SLOT + o * APITCH + i * 2) =
            __float2half_rn(b2[e]);
    }
}

// ---------------------------------------------------------------------------
// PTX helpers
// ---------------------------------------------------------------------------
__device__ __forceinline__ void cp16(uint32_t s, const void* g) {
    asm volatile("cp.async.cg.shared.global [%0], [%1], 16;" :: "r"(s), "l"(g));
}
__device__ __forceinline__ void ldsm_x4(uint32_t* r, uint32_t addr) {
    asm volatile("ldmatrix.sync.aligned.m8n8.x4.shared.b16 {%0,%1,%2,%3}, [%4];"
        : "=r"(r[0]), "=r"(r[1]), "=r"(r[2]), "=r"(r[3]) : "r"(addr));
}
__device__ __forceinline__ void mma_f16(float* d, const uint32_t* a,
                                        uint32_t b0, uint32_t b1) {
    asm volatile(
        "mma.sync.aligned.m16n8k16.row.col.f32.f16.f16.f32 "
        "{%0,%1,%2,%3}, {%4,%5,%6,%7}, {%8,%9}, {%0,%1,%2,%3};"
        : "+f"(d[0]), "+f"(d[1]), "+f"(d[2]), "+f"(d[3])
        : "r"(a[0]), "r"(a[1]), "r"(a[2]), "r"(a[3]), "r"(b0), "r"(b1));
}
__device__ __forceinline__ uint32_t hmul2u(uint32_t a, uint32_t f) {
    uint32_t d;
    asm("mul.rn.f16x2 %0, %1, %2;" : "=r"(d) : "r"(a), "r"(f));
    return d;
}
__device__ __forceinline__ uint32_t hdup(uint32_t smem_addr) {
    uint32_t h;
    asm volatile("ld.shared.u16 %0, [%1];" : "=r"(h) : "r"(smem_addr));
    return h | (h << 16);
}

// ---------------------------------------------------------------------------
// SMEM layout (bytes) — 102.5 KB total -> 2 CTAs/SM
// ---------------------------------------------------------------------------
#define SM_A    0u        // h fp16 tile 128 rows        (18432)
#define SM_F    18432u    // radial staging, then f fp16 (18432)
#define SM_B    36864u    // 3 stages x 18432            (55296)
#define SM_W1   92160u    // W1 fp32 [32][64]            (8192)
#define SM_WA   100352u   // Wa fp32 [16][64]            (4096)
#define SM_B1   104448u   // b1 fp32 [64]                (256)
#define SM_BA   104704u   // ba fp32 [64]                (256)
#define SMEM_BYTES 104960

// ---------------------------------------------------------------------------
// Main kernel: 128 tokens/CTA, 8 warps, 2 CTAs/SM.
// Warp = (m-pair, n-half): 32 rows (2 m16 bands) x 32 cols (4 n8 tiles)
// ---------------------------------------------------------------------------
__global__ __launch_bounds__(THREADS, 2)
void tp_main(const float* __restrict__ features,
             const float* __restrict__ radial,
             const float* __restrict__ angular,
             const float* __restrict__ W1,
             const float* __restrict__ b1,
             const float* __restrict__ Wa,
             const float* __restrict__ ba,
             float* __restrict__ out)
{
    extern __shared__ __align__(1024) uint8_t smem[];
    const uint32_t sb = (uint32_t)__cvta_generic_to_shared(smem);
    const int tid  = threadIdx.x;
    const int lane = tid & 31;
    const int warp = tid >> 5;
    const int n0   = blockIdx.x * TILE_M;

    // ---- cp.async: prefetch stages 0..2 (slot pairs 0..2) ----
#pragma unroll
    for (int s = 0; s < NSTAGE; s++) {
        const uint8_t* src = g_stream + (size_t)s * STAGE;
        for (int e = tid; e < 1152; e += THREADS)
            cp16(sb + SM_B + s * STAGE + e * 16, src + e * 16);
        asm volatile("cp.async.commit_group;");
    }

    // ---- stage radial (into SM_F region, pitch 33 fp32) + weights ----
    float* srad = (float*)(smem + SM_F);     // [128][33]
    float* sW1  = (float*)(smem + SM_W1);
    float* sWa  = (float*)(smem + SM_WA);
    float* sb1_ = (float*)(smem + SM_B1);
    float* sba_ = (float*)(smem + SM_BA);

    for (int e = tid; e < TILE_M * RAD_F; e += THREADS) {
        const int m = e >> 5, r = e & 31;
        srad[m * 33 + r] = radial[(size_t)(n0 + m) * RAD_F + r];
    }
    for (int e = tid; e < RAD_F * HID; e += THREADS) sW1[e] = W1[e];
    for (int e = tid; e < ANG_F * OUT_F; e += THREADS) sWa[e] = Wa[e];
    if (tid < HID)   sb1_[tid] = b1[tid];
    else if (tid < HID + OUT_F) sba_[tid - HID] = ba[tid - HID];
    __syncthreads();

    // ---- h = silu(radial@W1+b1) -> A tile (fp16) ----
    {
        const int j  = tid & 63;
        const int mb = tid >> 6;
#pragma unroll 4
        for (int s = 0; s < TILE_M / 4; s++) {
            const int m = mb + s * 4;
            float a = sb1_[j];
#pragma unroll
            for (int r = 0; r < RAD_F; r++)
                a = fmaf(srad[m * 33 + r], sW1[r * HID + j], a);
            const float hv = a / (1.0f + expf(-a));
            *(__half*)(smem + SM_A + m * APITCH + j * 2) = __float2half_rn(hv);
        }
    }
    __syncthreads();   // radial fully consumed; SM_F free for f tile

    // ---- f fp16 tile -> SM_F (overwrites radial staging) ----
    for (int e = tid; e < TILE_M * IN_F; e += THREADS) {
        const int m = e >> 6, c = e & 63;
        const float v = features[(size_t)(n0 + m) * IN_F + c];
        *(__half*)(smem + SM_F + m * APITCH + c * 2) = __float2half_rn(v);
    }

    // ---- warp decomposition ----
    const int mpair = warp >> 1;          // rows mpair*32 .. +31
    const int nhalf = warp & 1;           // cols nhalf*32 .. +31
    const int m0    = mpair * 32;
    const int nc0   = nhalf * 32;

    const uint32_t a_row  = ((lane >> 3) & 1) * 8 + (lane & 7);
    const uint32_t a_kadd = (lane >> 4) * 16;
    const uint32_t b_row  = ((lane >> 4) & 1) * 8 + (lane & 7);
    const uint32_t b_kadd = ((lane >> 3) & 1) * 16;
    const int r0 = lane >> 2;

    // ---- preload A (h) fragments for both bands ----
    uint32_t Ah0[4][4], Ah1[4][4];
    {
        const uint32_t base0 = sb + SM_A + (m0 + a_row) * APITCH + a_kadd;
        const uint32_t base1 = base0 + 16 * APITCH;
#pragma unroll
        for (int ks = 0; ks < 4; ks++) ldsm_x4(Ah0[ks], base0 + ks * 32);
#pragma unroll
        for (int ks = 0; ks < 4; ks++) ldsm_x4(Ah1[ks], base1 + ks * 32);
    }

    float acc0[4][4], acc1[4][4];
#pragma unroll
    for (int nt = 0; nt < 4; nt++)
#pragma unroll
        for (int j = 0; j < 4; j++) { acc0[nt][j] = 0.0f; acc1[nt][j] = 0.0f; }

    const uint32_t fa0 = sb + SM_F + (m0 + r0) * APITCH;   // band0 row r0
    const uint32_t fa1 = fa0 + 8 * APITCH;                 // band0 row r0+8
    const uint32_t fa2 = fa0 + 16 * APITCH;                // band1 row r0
    const uint32_t fa3 = fa0 + 24 * APITCH;                // band1 row r0+8

    const uint32_t brow_off = (nc0 + b_row) * APITCH + b_kadd;

    // ---- 32 pair-iterations (slots 0..63); 3-stage pipeline, 1 sync/iter ----
    for (int j = 0; j < 32; j++) {
        asm volatile("cp.async.wait_group 2;");
        __syncthreads();

        const uint32_t bbase = sb + SM_B + (j % 3) * STAGE;

#pragma unroll
        for (int half = 0; half < 2; half++) {
            const int i = 2 * j + half;
            const uint32_t sbb = bbase + half * B_SLOT + brow_off;

            const uint32_t f0 = hdup(fa0 + i * 2);
            const uint32_t f1 = hdup(fa1 + i * 2);
            const uint32_t f2 = hdup(fa2 + i * 2);
            const uint32_t f3 = hdup(fa3 + i * 2);

#pragma unroll
            for (int ks = 0; ks < 4; ks++) {
                uint32_t bh[8];
                ldsm_x4(bh,     sbb + ks * 32);
                ldsm_x4(bh + 4, sbb + 16 * APITCH + ks * 32);

                // A frag regs {0,2} = row r0, {1,3} = row r0+8
                uint32_t As0[4], As1[4];
                As0[0] = hmul2u(Ah0[ks][0], f0);
                As0[1] = hmul2u(Ah0[ks][1], f1);
                As0[2] = hmul2u(Ah0[ks][2], f0);
                As0[3] = hmul2u(Ah0[ks][3], f1);
                As1[0] = hmul2u(Ah1[ks][0], f2);
                As1[1] = hmul2u(Ah1[ks][1], f3);
                As1[2] = hmul2u(Ah1[ks][2], f2);
                As1[3] = hmul2u(Ah1[ks][3], f3);

#pragma unroll
                for (int nt = 0; nt < 4; nt++) {
                    const uint32_t b0  = bh[(nt >> 1) * 4 + (nt & 1) * 2];
                    const uint32_t b1v = bh[(nt >> 1) * 4 + (nt & 1) * 2 + 1];
                    mma_f16(acc0[nt], As0, b0, b1v);
                    mma_f16(acc1[nt], As1, b0, b1v);
                }
            }
        }

        __syncthreads();   // all warps done with stage (j%3) before refill
        if (j + 3 <= 32) {
            const uint8_t* src = g_stream + (size_t)(j + 3) * STAGE;
            const uint32_t dst = sb + SM_B + ((j + 3) % 3) * STAGE;
            for (int e = tid; e < 1152; e += THREADS)
                cp16(dst + e * 16, src + e * 16);
            asm volatile("cp.async.commit_group;");
        }
    }

    // ---- pair-iteration 32: slot 64 = b2 (F fragments), slot 65 skipped ----
    {
        asm volatile("cp.async.wait_group 0;");
        __syncthreads();

        const uint32_t b2b = sb + SM_B + (32 % 3) * STAGE + brow_off;
        const uint32_t base0 = sb + SM_F + (m0 + a_row) * APITCH + a_kadd;
        const uint32_t base1 = base0 + 16 * APITCH;
#pragma unroll
        for (int ks = 0; ks < 4; ks++) {
            uint32_t Fh0[4], Fh1[4], bh[8];
            ldsm_x4(Fh0, base0 + ks * 32);
            ldsm_x4(Fh1, base1 + ks * 32);
            ldsm_x4(bh,     b2b + ks * 32);
            ldsm_x4(bh + 4, b2b + 16 * APITCH + ks * 32);
#pragma unroll
            for (int nt = 0; nt < 4; nt++) {
                const uint32_t b0  = bh[(nt >> 1) * 4 + (nt & 1) * 2];
                const uint32_t b1v = bh[(nt >> 1) * 4 + (nt & 1) * 2 + 1];
                mma_f16(acc0[nt], Fh0, b0, b1v);
                mma_f16(acc1[nt], Fh1, b0, b1v);
            }
        }
    }

    // ---- epilogue: ang = angular@Wa+ba (angular direct from gmem) ----
    const int gc = (lane & 3) * 2;
#pragma unroll
    for (int band = 0; band < 2; band++) {
        float (*ac)[4] = band ? acc1 : acc0;
#pragma unroll
        for (int rs = 0; rs < 2; rs++) {    // D frag: {0,1}=row r0, {2,3}=row r0+8
            const int m = m0 + band * 16 + rs * 8 + r0;
            float sa[16];
            {
                const float4* ap = (const float4*)(angular + (size_t)(n0 + m) * ANG_F);
#pragma unroll
                for (int q4 = 0; q4 < 4; q4++) {
                    float4 v = __ldg(ap + q4);
                    sa[q4 * 4 + 0] = v.x; sa[q4 * 4 + 1] = v.y;
                    sa[q4 * 4 + 2] = v.z; sa[q4 * 4 + 3] = v.w;
                }
            }

            const size_t orow = (size_t)(n0 + m) * OUT_F;
#pragma unroll
            for (int nt = 0; nt < 4; nt++) {
                const int c0 = nc0 + nt * 8 + gc;
                float a0 = sba_[c0], a1 = sba_[c0 + 1];
#pragma unroll
                for (int q = 0; q < 16; q++) {
                    a0 = fmaf(sa[q], sWa[q * 64 + c0], a0);
                    a1 = fmaf(sa[q], sWa[q * 64 + c0 + 1], a1);
                }
                float2 o;
                o.x = ac[nt][rs * 2 + 0] * a0;
                o.y = ac[nt][rs * 2 + 1] * a1;
                *(float2*)(out + orow + c0) = o;
            }
        }
    }
}

// ---------------------------------------------------------------------------
// Launch
// ---------------------------------------------------------------------------
extern "C" void kernel_launch(void* const* d_in, const int* in_sizes, int n_in,
                              void* d_out, int out_size)
{
    const float* features = (const float*)d_in[0];
    const float* radial   = (const float*)d_in[1];
    const float* angular  = (const float*)d_in[2];
    const float* W1       = (const float*)d_in[3];
    const float* b1       = (const float*)d_in[4];
    const float* W2       = (const float*)d_in[5];
    const float* b2       = (const float*)d_in[6];
    const float* Wa       = (const float*)d_in[7];
    const float* ba       = (const float*)d_in[8];
    float* out = (float*)d_out;
    (void)in_sizes; (void)n_in; (void)out_size;

    cudaFuncSetAttribute(tp_main, cudaFuncAttributeMaxDynamicSharedMemorySize, SMEM_BYTES);

    tp_wsplit<<<(64 * 4096 + 4096 + THREADS - 1) / THREADS, THREADS>>>(W2, b2);
    tp_main<<<NTILES, THREADS, SMEM_BYTES>>>(features, radial, angular,
                                             W1, b1, Wa, ba, out);
}

// round 11
// speedup vs baseline: 1.1881x; 1.0509x over previous
#include <cuda_runtime.h>
#include <cuda_fp16.h>
#include <math.h>
#include <stdint.h>

#define NTOK  65536
#define IN_F  64
#define OUT_F 64
#define RAD_F 32
#define ANG_F 16
#define HID   64

#define TILE_M   128
#define NTILES   (NTOK / TILE_M)   // 512
#define THREADS  256

#define APITCH   144               // 64 fp16 = 128B + 16B pad (ldsm conflict-free)
#define B_SLOT   9216              // 64 rows * 144 B
#define STAGE    (2 * B_SLOT)      // 2 i-slots per stage = 18432

// ---------------------------------------------------------------------------
// Device-global scratch: 66-slot stream (W2 0..63, b2 at 64, 65 = padding)
// ---------------------------------------------------------------------------
__device__ __align__(1024) uint8_t g_stream[(size_t)66 * B_SLOT];

__global__ void tp_wsplit(const float* __restrict__ W2, const float* __restrict__ b2)
{
    const int idx = blockIdx.x * THREADS + threadIdx.x;
    if (idx < 64 * 4096) {
        const int k  = idx >> 12;
        const int io = idx & 4095;
        const int o  = io & 63;
        const int i  = io >> 6;
        *(__half*)(g_stream + (size_t)i * B_SLOT + o * APITCH + k * 2) =
            __float2half_rn(W2[idx]);
    } else if (idx < 64 * 4096 + 4096) {
        const int e = idx - 64 * 4096;
        const int i = e >> 6;
        const int o = e & 63;
        *(__half*)(g_stream + (size_t)64 * B_SLOT + o * APITCH + i * 2) =
            __float2half_rn(b2[e]);
    }
}

// ---------------------------------------------------------------------------
// PTX helpers
// ---------------------------------------------------------------------------
__device__ __forceinline__ void cp16(uint32_t s, const void* g) {
    asm volatile("cp.async.cg.shared.global [%0], [%1], 16;" :: "r"(s), "l"(g));
}
__device__ __forceinline__ void ldsm_x4(uint32_t* r, uint32_t addr) {
    asm volatile("ldmatrix.sync.aligned.m8n8.x4.shared.b16 {%0,%1,%2,%3}, [%4];"
        : "=r"(r[0]), "=r"(r[1]), "=r"(r[2]), "=r"(r[3]) : "r"(addr));
}
__device__ __forceinline__ void mma_f16(float* d, const uint32_t* a,
                                        uint32_t b0, uint32_t b1) {
    asm volatile(
        "mma.sync.aligned.m16n8k16.row.col.f32.f16.f16.f32 "
        "{%0,%1,%2,%3}, {%4,%5,%6,%7}, {%8,%9}, {%0,%1,%2,%3};"
        : "+f"(d[0]), "+f"(d[1]), "+f"(d[2]), "+f"(d[3])
        : "r"(a[0]), "r"(a[1]), "r"(a[2]), "r"(a[3]), "r"(b0), "r"(b1));
}
__device__ __forceinline__ uint32_t hmul2u(uint32_t a, uint32_t f) {
    uint32_t d;
    asm("mul.rn.f16x2 %0, %1, %2;" : "=r"(d) : "r"(a), "r"(f));
    return d;
}
__device__ __forceinline__ uint32_t lds32(uint32_t addr) {
    uint32_t v;
    asm volatile("ld.shared.b32 %0, [%1];" : "=r"(v) : "r"(addr));
    return v;
}

// ---------------------------------------------------------------------------
// SMEM layout (bytes) — 104960 total -> 2 CTAs/SM
// ---------------------------------------------------------------------------
#define SM_B    0u        // 4 stages x 18432 = 73728; A tile ALIASES stage 3
#define SM_A    55296u    // = SM_B + 3*STAGE (h tile, read once into frags)
#define SM_F    73728u    // radial staging, then f fp16 tile (18432)
#define SM_W1   92160u    // W1 fp32 [32][64]  (8192)
#define SM_WA   100352u   // Wa fp32 [16][64]  (4096)
#define SM_B1   104448u   // b1 fp32 [64]      (256)
#define SM_BA   104704u   // ba fp32 [64]      (256)
#define SMEM_BYTES 104960

// ---------------------------------------------------------------------------
// Main kernel: 128 tokens/CTA, 8 warps, 2 CTAs/SM, warp = 32 rows x 32 cols.
// 4-stage pipeline, ONE __syncthreads per pair-iteration.
// ---------------------------------------------------------------------------
__global__ __launch_bounds__(THREADS, 2)
void tp_main(const float* __restrict__ features,
             const float* __restrict__ radial,
             const float* __restrict__ angular,
             const float* __restrict__ W1,
             const float* __restrict__ b1,
             const float* __restrict__ Wa,
             const float* __restrict__ ba,
             float* __restrict__ out)
{
    extern __shared__ __align__(1024) uint8_t smem[];
    const uint32_t sb = (uint32_t)__cvta_generic_to_shared(smem);
    const int tid  = threadIdx.x;
    const int lane = tid & 31;
    const int warp = tid >> 5;
    const int n0   = blockIdx.x * TILE_M;

    // ---- prologue cp.async: pairs 0..2 -> bufs 0..2 (groups 0..2) ----
#pragma unroll
    for (int s = 0; s < 3; s++) {
        const uint8_t* src = g_stream + (size_t)s * STAGE;
        for (int e = tid; e < 1152; e += THREADS)
            cp16(sb + SM_B + s * STAGE + e * 16, src + e * 16);
        asm volatile("cp.async.commit_group;");
    }

    // ---- stage radial (into SM_F region) + weights ----
    float* srad = (float*)(smem + SM_F);     // [128][33]
    float* sW1  = (float*)(smem + SM_W1);
    float* sWa  = (float*)(smem + SM_WA);
    float* sb1_ = (float*)(smem + SM_B1);
    float* sba_ = (float*)(smem + SM_BA);

    for (int e = tid; e < TILE_M * RAD_F; e += THREADS) {
        const int m = e >> 5, r = e & 31;
        srad[m * 33 + r] = radial[(size_t)(n0 + m) * RAD_F + r];
    }
    for (int e = tid; e < RAD_F * HID; e += THREADS) sW1[e] = W1[e];
    for (int e = tid; e < ANG_F * OUT_F; e += THREADS) sWa[e] = Wa[e];
    if (tid < HID)   sb1_[tid] = b1[tid];
    else if (tid < HID + OUT_F) sba_[tid - HID] = ba[tid - HID];
    __syncthreads();

    // ---- h = silu(radial@W1+b1) -> A tile (aliased onto buf 3) ----
    {
        const int j  = tid & 63;
        const int mb = tid >> 6;
#pragma unroll 4
        for (int s = 0; s < TILE_M / 4; s++) {
            const int m = mb + s * 4;
            float a = sb1_[j];
#pragma unroll
            for (int r = 0; r < RAD_F; r++)
                a = fmaf(srad[m * 33 + r], sW1[r * HID + j], a);
            const float hv = a / (1.0f + expf(-a));
            *(__half*)(smem + SM_A + m * APITCH + j * 2) = __float2half_rn(hv);
        }
    }
    __syncthreads();   // A complete; radial fully consumed

    // ---- warp decomposition (validated R9) ----
    const int mpair = warp >> 1;
    const int nhalf = warp & 1;
    const int m0    = mpair * 32;
    const int nc0   = nhalf * 32;

    const uint32_t a_row  = ((lane >> 3) & 1) * 8 + (lane & 7);
    const uint32_t a_kadd = (lane >> 4) * 16;
    const uint32_t b_row  = ((lane >> 4) & 1) * 8 + (lane & 7);
    const uint32_t b_kadd = ((lane >> 3) & 1) * 16;
    const int r0 = lane >> 2;

    // ---- load A (h) fragments; write f fp16 tile over radial ----
    uint32_t Ah0[4][4], Ah1[4][4];
    {
        const uint32_t base0 = sb + SM_A + (m0 + a_row) * APITCH + a_kadd;
        const uint32_t base1 = base0 + 16 * APITCH;
#pragma unroll
        for (int ks = 0; ks < 4; ks++) ldsm_x4(Ah0[ks], base0 + ks * 32);
#pragma unroll
        for (int ks = 0; ks < 4; ks++) ldsm_x4(Ah1[ks], base1 + ks * 32);
    }
    for (int e = tid; e < TILE_M * IN_F; e += THREADS) {
        const int m = e >> 6, c = e & 63;
        const float v = features[(size_t)(n0 + m) * IN_F + c];
        *(__half*)(smem + SM_F + m * APITCH + c * 2) = __float2half_rn(v);
    }
    __syncthreads();   // all warps have A frags; F tile visible

    // ---- now safe to overwrite buf 3 with pair 3 (consumed at iter 3) ----
    {
        const uint8_t* src = g_stream + (size_t)3 * STAGE;
        for (int e = tid; e < 1152; e += THREADS)
            cp16(sb + SM_B + 3 * STAGE + e * 16, src + e * 16);
        asm volatile("cp.async.commit_group;");   // group 3
    }

    float acc0[4][4], acc1[4][4];
#pragma unroll
    for (int nt = 0; nt < 4; nt++)
#pragma unroll
        for (int j = 0; j < 4; j++) { acc0[nt][j] = 0.0f; acc1[nt][j] = 0.0f; }

    const uint32_t fa0 = sb + SM_F + (m0 + r0) * APITCH;   // band0 row r0
    const uint32_t fa1 = fa0 + 8 * APITCH;
    const uint32_t fa2 = fa0 + 16 * APITCH;
    const uint32_t fa3 = fa0 + 24 * APITCH;

    const uint32_t brow_off = (nc0 + b_row) * APITCH + b_kadd;

    // ---- 32 pair-iterations (pairs 0..31); ONE sync per iter ----
    for (int j = 0; j < 32; j++) {
        asm volatile("cp.async.wait_group 2;");   // pair j resident
        __syncthreads();                          // all warps done with iter j-1

        // refill: pair j+3 -> buf (j+3)&3 (holds pair j-1, consumed last iter)
        if (j >= 1 && j <= 29) {
            const uint8_t* src = g_stream + (size_t)(j + 3) * STAGE;
            const uint32_t dst = sb + SM_B + ((j + 3) & 3) * STAGE;
            for (int e = tid; e < 1152; e += THREADS)
                cp16(dst + e * 16, src + e * 16);
            asm volatile("cp.async.commit_group;");
        }

        const uint32_t bbase = sb + SM_B + (j & 3) * STAGE;

#pragma unroll
        for (int half = 0; half < 2; half++) {
            const uint32_t sbb = bbase + half * B_SLOT + brow_off;

            // f pair (2j, 2j+1): one b32 load per row, PRMT splats
            const uint32_t v0 = lds32(fa0 + j * 4);
            const uint32_t v1 = lds32(fa1 + j * 4);
            const uint32_t v2 = lds32(fa2 + j * 4);
            const uint32_t v3 = lds32(fa3 + j * 4);
            const uint32_t sel = half ? 0x3232u : 0x1010u;
            const uint32_t f0 = __byte_perm(v0, v0, sel);
            const uint32_t f1 = __byte_perm(v1, v1, sel);
            const uint32_t f2 = __byte_perm(v2, v2, sel);
            const uint32_t f3 = __byte_perm(v3, v3, sel);

#pragma unroll
            for (int ks = 0; ks < 4; ks++) {
                uint32_t bh[8];
                ldsm_x4(bh,     sbb + ks * 32);
                ldsm_x4(bh + 4, sbb + 16 * APITCH + ks * 32);

                // A frag regs {0,2} = row r0, {1,3} = row r0+8
                uint32_t As0[4], As1[4];
                As0[0] = hmul2u(Ah0[ks][0], f0);
                As0[1] = hmul2u(Ah0[ks][1], f1);
                As0[2] = hmul2u(Ah0[ks][2], f0);
                As0[3] = hmul2u(Ah0[ks][3], f1);
                As1[0] = hmul2u(Ah1[ks][0], f2);
                As1[1] = hmul2u(Ah1[ks][1], f3);
                As1[2] = hmul2u(Ah1[ks][2], f2);
                As1[3] = hmul2u(Ah1[ks][3], f3);

#pragma unroll
                for (int nt = 0; nt < 4; nt++) {
                    const uint32_t b0  = bh[(nt >> 1) * 4 + (nt & 1) * 2];
                    const uint32_t b1v = bh[(nt >> 1) * 4 + (nt & 1) * 2 + 1];
                    mma_f16(acc0[nt], As0, b0, b1v);
                    mma_f16(acc1[nt], As1, b0, b1v);
                }
            }
        }
    }

    // ---- b2 pass: pair 32 in buf 0, half 0; A = unscaled f fragments ----
    {
        asm volatile("cp.async.wait_group 0;");
        __syncthreads();

        const uint32_t b2b   = sb + SM_B + 0 * STAGE + brow_off;
        const uint32_t base0 = sb + SM_F + (m0 + a_row) * APITCH + a_kadd;
        const uint32_t base1 = base0 + 16 * APITCH;
#pragma unroll
        for (int ks = 0; ks < 4; ks++) {
            uint32_t Fh0[4], Fh1[4], bh[8];
            ldsm_x4(Fh0, base0 + ks * 32);
            ldsm_x4(Fh1, base1 + ks * 32);
            ldsm_x4(bh,     b2b + ks * 32);
            ldsm_x4(bh + 4, b2b + 16 * APITCH + ks * 32);
#pragma unroll
            for (int nt = 0; nt < 4; nt++) {
                const uint32_t b0  = bh[(nt >> 1) * 4 + (nt & 1) * 2];
                const uint32_t b1v = bh[(nt >> 1) * 4 + (nt & 1) * 2 + 1];
                mma_f16(acc0[nt], Fh0, b0, b1v);
                mma_f16(acc1[nt], Fh1, b0, b1v);
            }
        }
    }

    // ---- epilogue: ang = angular@Wa+ba (angular from gmem), mult, store ----
    const int gc = (lane & 3) * 2;
#pragma unroll
    for (int band = 0; band < 2; band++) {
        float (*ac)[4] = band ? acc1 : acc0;
#pragma unroll
        for (int rs = 0; rs < 2; rs++) {
            const int m = m0 + band * 16 + rs * 8 + r0;
            float sa[16];
            {
                const float4* ap = (const float4*)(angular + (size_t)(n0 + m) * ANG_F);
#pragma unroll
                for (int q4 = 0; q4 < 4; q4++) {
                    float4 v = __ldg(ap + q4);
                    sa[q4 * 4 + 0] = v.x; sa[q4 * 4 + 1] = v.y;
                    sa[q4 * 4 + 2] = v.z; sa[q4 * 4 + 3] = v.w;
                }
            }
            const size_t orow = (size_t)(n0 + m) * OUT_F;
#pragma unroll
            for (int nt = 0; nt < 4; nt++) {
                const int c0 = nc0 + nt * 8 + gc;
                float a0 = sba_[c0], a1 = sba_[c0 + 1];
#pragma unroll
                for (int q = 0; q < 16; q++) {
                    a0 = fmaf(sa[q], sWa[q * 64 + c0], a0);
                    a1 = fmaf(sa[q], sWa[q * 64 + c0 + 1], a1);
                }
                float2 o;
                o.x = ac[nt][rs * 2 + 0] * a0;
                o.y = ac[nt][rs * 2 + 1] * a1;
                *(float2*)(out + orow + c0) = o;
            }
        }
    }
}

// ---------------------------------------------------------------------------
// Launch
// ---------------------------------------------------------------------------
extern "C" void kernel_launch(void* const* d_in, const int* in_sizes, int n_in,
                              void* d_out, int out_size)
{
    const float* features = (const float*)d_in[0];
    const float* radial   = (const float*)d_in[1];
    const float* angular  = (const float*)d_in[2];
    const float* W1       = (const float*)d_in[3];
    const float* b1       = (const float*)d_in[4];
    const float* W2       = (const float*)d_in[5];
    const float* b2       = (const float*)d_in[6];
    const float* Wa       = (const float*)d_in[7];
    const float* ba       = (const float*)d_in[8];
    float* out = (float*)d_out;
    (void)in_sizes; (void)n_in; (void)out_size;

    cudaFuncSetAttribute(tp_main, cudaFuncAttributeMaxDynamicSharedMemorySize, SMEM_BYTES);

    tp_wsplit<<<(64 * 4096 + 4096 + THREADS - 1) / THREADS, THREADS>>>(W2, b2);
    tp_main<<<NTILES, THREADS, SMEM_BYTES>>>(features, radial, angular,
                                             W1, b1, Wa, ba, out);
}

// round 12
// speedup vs baseline: 1.2028x; 1.0124x over previous
#include <cuda_runtime.h>
#include <cuda_fp16.h>
#include <math.h>
#include <stdint.h>

#define NTOK  65536
#define IN_F  64
#define OUT_F 64
#define RAD_F 32
#define ANG_F 16
#define HID   64

#define TILE_M   128
#define NTILES   (NTOK / TILE_M)   // 512
#define THREADS  256

#define APITCH   144               // 64 fp16 = 128B + 16B pad (ldsm conflict-free)
#define B_SLOT   9216              // 64 rows * 144 B
#define STAGE    (2 * B_SLOT)      // 2 i-slots per stage = 18432

// ---------------------------------------------------------------------------
// Device-global scratch: 66-slot stream (W2 0..63, b2 at 64, 65 = padding)
// ---------------------------------------------------------------------------
__device__ __align__(1024) uint8_t g_stream[(size_t)66 * B_SLOT];

__global__ void tp_wsplit(const float* __restrict__ W2, const float* __restrict__ b2)
{
    const int idx = blockIdx.x * THREADS + threadIdx.x;
    if (idx < 64 * 4096) {
        const int k  = idx >> 12;
        const int io = idx & 4095;
        const int o  = io & 63;
        const int i  = io >> 6;
        *(__half*)(g_stream + (size_t)i * B_SLOT + o * APITCH + k * 2) =
            __float2half_rn(W2[idx]);
    } else if (idx < 64 * 4096 + 4096) {
        const int e = idx - 64 * 4096;
        const int i = e >> 6;
        const int o = e & 63;
        *(__half*)(g_stream + (size_t)64 * B_SLOT + o * APITCH + i * 2) =
            __float2half_rn(b2[e]);
    }
}

// ---------------------------------------------------------------------------
// PTX helpers
// ---------------------------------------------------------------------------
__device__ __forceinline__ void cp16(uint32_t s, const void* g) {
    asm volatile("cp.async.cg.shared.global [%0], [%1], 16;" :: "r"(s), "l"(g));
}
__device__ __forceinline__ void ldsm_x4(uint32_t* r, uint32_t addr) {
    asm volatile("ldmatrix.sync.aligned.m8n8.x4.shared.b16 {%0,%1,%2,%3}, [%4];"
        : "=r"(r[0]), "=r"(r[1]), "=r"(r[2]), "=r"(r[3]) : "r"(addr));
}
__device__ __forceinline__ void mma_f16(float* d, const uint32_t* a,
                                        uint32_t b0, uint32_t b1) {
    asm volatile(
        "mma.sync.aligned.m16n8k16.row.col.f32.f16.f16.f32 "
        "{%0,%1,%2,%3}, {%4,%5,%6,%7}, {%8,%9}, {%0,%1,%2,%3};"
        : "+f"(d[0]), "+f"(d[1]), "+f"(d[2]), "+f"(d[3])
        : "r"(a[0]), "r"(a[1]), "r"(a[2]), "r"(a[3]), "r"(b0), "r"(b1));
}
__device__ __forceinline__ uint32_t hmul2u(uint32_t a, uint32_t f) {
    uint32_t d;
    asm("mul.rn.f16x2 %0, %1, %2;" : "=r"(d) : "r"(a), "r"(f));
    return d;
}
__device__ __forceinline__ uint32_t lds32(uint32_t addr) {
    uint32_t v;
    asm volatile("ld.shared.b32 %0, [%1];" : "=r"(v) : "r"(addr));
    return v;
}
// silu via single-MUFU tanh: x*sigmoid(x) = 0.5x*(1+tanh(x/2))
__device__ __forceinline__ float silu_tanh(float x) {
    float t;
    asm("tanh.approx.f32 %0, %1;" : "=f"(t) : "f"(0.5f * x));
    const float hx = 0.5f * x;
    return fmaf(hx, t, hx);
}

// ---------------------------------------------------------------------------
// SMEM layout (bytes) — 104960 total -> 2 CTAs/SM
// ---------------------------------------------------------------------------
#define SM_B    0u        // 4 stages x 18432 = 73728; A tile ALIASES stage 3
#define SM_A    55296u    // = SM_B + 3*STAGE (h tile, read once into frags)
#define SM_F    73728u    // radial staging, then f fp16 tile (18432)
#define SM_W1   92160u    // W1 fp32 [32][64]  (8192)
#define SM_WA   100352u   // Wa fp32 [16][64]  (4096)
#define SM_B1   104448u   // b1 fp32 [64]      (256)
#define SM_BA   104704u   // ba fp32 [64]      (256)
#define SMEM_BYTES 104960

// ---------------------------------------------------------------------------
// Main kernel: 128 tokens/CTA, 8 warps, 2 CTAs/SM, warp = 32 rows x 32 cols.
// 4-stage pipeline, ONE __syncthreads per pair-iteration.
// ---------------------------------------------------------------------------
__global__ __launch_bounds__(THREADS, 2)
void tp_main(const float* __restrict__ features,
             const float* __restrict__ radial,
             const float* __restrict__ angular,
             const float* __restrict__ W1,
             const float* __restrict__ b1,
             const float* __restrict__ Wa,
             const float* __restrict__ ba,
             float* __restrict__ out)
{
    extern __shared__ __align__(1024) uint8_t smem[];
    const uint32_t sb = (uint32_t)__cvta_generic_to_shared(smem);
    const int tid  = threadIdx.x;
    const int lane = tid & 31;
    const int warp = tid >> 5;
    const int n0   = blockIdx.x * TILE_M;

    // ---- prologue cp.async: pairs 0..2 -> bufs 0..2 (groups 0..2) ----
#pragma unroll
    for (int s = 0; s < 3; s++) {
        const uint8_t* src = g_stream + (size_t)s * STAGE;
        for (int e = tid; e < 1152; e += THREADS)
            cp16(sb + SM_B + s * STAGE + e * 16, src + e * 16);
        asm volatile("cp.async.commit_group;");
    }

    // ---- stage radial (into SM_F region) + weights ----
    float* srad = (float*)(smem + SM_F);     // [128][33]
    float* sW1  = (float*)(smem + SM_W1);
    float* sWa  = (float*)(smem + SM_WA);
    float* sb1_ = (float*)(smem + SM_B1);
    float* sba_ = (float*)(smem + SM_BA);

    for (int e = tid; e < TILE_M * RAD_F; e += THREADS) {
        const int m = e >> 5, r = e & 31;
        srad[m * 33 + r] = radial[(size_t)(n0 + m) * RAD_F + r];
    }
    for (int e = tid; e < RAD_F * HID; e += THREADS) sW1[e] = W1[e];
    for (int e = tid; e < ANG_F * OUT_F; e += THREADS) sWa[e] = Wa[e];
    if (tid < HID)   sb1_[tid] = b1[tid];
    else if (tid < HID + OUT_F) sba_[tid - HID] = ba[tid - HID];
    __syncthreads();

    // ---- h = silu(radial@W1+b1) -> A tile (aliased onto buf 3) ----
    // single-MUFU silu (tanh.approx) — halves SFU-pipe work vs exp+rcp
    {
        const int j  = tid & 63;
        const int mb = tid >> 6;
#pragma unroll 4
        for (int s = 0; s < TILE_M / 4; s++) {
            const int m = mb + s * 4;
            float a = sb1_[j];
#pragma unroll
            for (int r = 0; r < RAD_F; r++)
                a = fmaf(srad[m * 33 + r], sW1[r * HID + j], a);
            const float hv = silu_tanh(a);
            *(__half*)(smem + SM_A + m * APITCH + j * 2) = __float2half_rn(hv);
        }
    }
    __syncthreads();   // A complete; radial fully consumed

    // ---- warp decomposition (validated R9/R11) ----
    const int mpair = warp >> 1;
    const int nhalf = warp & 1;
    const int m0    = mpair * 32;
    const int nc0   = nhalf * 32;

    const uint32_t a_row  = ((lane >> 3) & 1) * 8 + (lane & 7);
    const uint32_t a_kadd = (lane >> 4) * 16;
    const uint32_t b_row  = ((lane >> 4) & 1) * 8 + (lane & 7);
    const uint32_t b_kadd = ((lane >> 3) & 1) * 16;
    const int r0 = lane >> 2;

    // ---- load A (h) fragments; write f fp16 tile over radial ----
    uint32_t Ah0[4][4], Ah1[4][4];
    {
        const uint32_t base0 = sb + SM_A + (m0 + a_row) * APITCH + a_kadd;
        const uint32_t base1 = base0 + 16 * APITCH;
#pragma unroll
        for (int ks = 0; ks < 4; ks++) ldsm_x4(Ah0[ks], base0 + ks * 32);
#pragma unroll
        for (int ks = 0; ks < 4; ks++) ldsm_x4(Ah1[ks], base1 + ks * 32);
    }
    for (int e = tid; e < TILE_M * IN_F; e += THREADS) {
        const int m = e >> 6, c = e & 63;
        const float v = features[(size_t)(n0 + m) * IN_F + c];
        *(__half*)(smem + SM_F + m * APITCH + c * 2) = __float2half_rn(v);
    }
    __syncthreads();   // all warps have A frags; F tile visible

    // ---- now safe to overwrite buf 3 with pair 3 (consumed at iter 3) ----
    {
        const uint8_t* src = g_stream + (size_t)3 * STAGE;
        for (int e = tid; e < 1152; e += THREADS)
            cp16(sb + SM_B + 3 * STAGE + e * 16, src + e * 16);
        asm volatile("cp.async.commit_group;");   // group 3
    }

    float acc0[4][4], acc1[4][4];
#pragma unroll
    for (int nt = 0; nt < 4; nt++)
#pragma unroll
        for (int j = 0; j < 4; j++) { acc0[nt][j] = 0.0f; acc1[nt][j] = 0.0f; }

    const uint32_t fa0 = sb + SM_F + (m0 + r0) * APITCH;   // band0 row r0
    const uint32_t fa1 = fa0 + 8 * APITCH;
    const uint32_t fa2 = fa0 + 16 * APITCH;
    const uint32_t fa3 = fa0 + 24 * APITCH;

    const uint32_t brow_off = (nc0 + b_row) * APITCH + b_kadd;

    // ---- 32 pair-iterations (pairs 0..31); ONE sync per iter ----
    for (int j = 0; j < 32; j++) {
        asm volatile("cp.async.wait_group 2;");   // pair j resident
        __syncthreads();                          // all warps done with iter j-1

        // refill: pair j+3 -> buf (j+3)&3 (holds pair j-1, consumed last iter)
        if (j >= 1 && j <= 29) {
            const uint8_t* src = g_stream + (size_t)(j + 3) * STAGE;
            const uint32_t dst = sb + SM_B + ((j + 3) & 3) * STAGE;
            for (int e = tid; e < 1152; e += THREADS)
                cp16(dst + e * 16, src + e * 16);
            asm volatile("cp.async.commit_group;");
        }

        const uint32_t bbase = sb + SM_B + (j & 3) * STAGE;

#pragma unroll
        for (int half = 0; half < 2; half++) {
            const uint32_t sbb = bbase + half * B_SLOT + brow_off;

            // f pair (2j, 2j+1): one b32 load per row, PRMT splats
            const uint32_t v0 = lds32(fa0 + j * 4);
            const uint32_t v1 = lds32(fa1 + j * 4);
            const uint32_t v2 = lds32(fa2 + j * 4);
            const uint32_t v3 = lds32(fa3 + j * 4);
            const uint32_t sel = half ? 0x3232u : 0x1010u;
            const uint32_t f0 = __byte_perm(v0, v0, sel);
            const uint32_t f1 = __byte_perm(v1, v1, sel);
            const uint32_t f2 = __byte_perm(v2, v2, sel);
            const uint32_t f3 = __byte_perm(v3, v3, sel);

#pragma unroll
            for (int ks = 0; ks < 4; ks++) {
                uint32_t bh[8];
                ldsm_x4(bh,     sbb + ks * 32);
                ldsm_x4(bh + 4, sbb + 16 * APITCH + ks * 32);

                // A frag regs {0,2} = row r0, {1,3} = row r0+8
                uint32_t As0[4], As1[4];
                As0[0] = hmul2u(Ah0[ks][0], f0);
                As0[1] = hmul2u(Ah0[ks][1], f1);
                As0[2] = hmul2u(Ah0[ks][2], f0);
                As0[3] = hmul2u(Ah0[ks][3], f1);
                As1[0] = hmul2u(Ah1[ks][0], f2);
                As1[1] = hmul2u(Ah1[ks][1], f3);
                As1[2] = hmul2u(Ah1[ks][2], f2);
                As1[3] = hmul2u(Ah1[ks][3], f3);

#pragma unroll
                for (int nt = 0; nt < 4; nt++) {
                    const uint32_t b0  = bh[(nt >> 1) * 4 + (nt & 1) * 2];
                    const uint32_t b1v = bh[(nt >> 1) * 4 + (nt & 1) * 2 + 1];
                    mma_f16(acc0[nt], As0, b0, b1v);
                    mma_f16(acc1[nt], As1, b0, b1v);
                }
            }
        }
    }

    // ---- b2 pass: pair 32 in buf 0, half 0; A = unscaled f fragments ----
    {
        asm volatile("cp.async.wait_group 0;");
        __syncthreads();

        const uint32_t b2b   = sb + SM_B + 0 * STAGE + brow_off;
        const uint32_t base0 = sb + SM_F + (m0 + a_row) * APITCH + a_kadd;
        const uint32_t base1 = base0 + 16 * APITCH;
#pragma unroll
        for (int ks = 0; ks < 4; ks++) {
            uint32_t Fh0[4], Fh1[4], bh[8];
            ldsm_x4(Fh0, base0 + ks * 32);
            ldsm_x4(Fh1, base1 + ks * 32);
            ldsm_x4(bh,     b2b + ks * 32);
            ldsm_x4(bh + 4, b2b + 16 * APITCH + ks * 32);
#pragma unroll
            for (int nt = 0; nt < 4; nt++) {
                const uint32_t b0  = bh[(nt >> 1) * 4 + (nt & 1) * 2];
                const uint32_t b1v = bh[(nt >> 1) * 4 + (nt & 1) * 2 + 1];
                mma_f16(acc0[nt], Fh0, b0, b1v);
                mma_f16(acc1[nt], Fh1, b0, b1v);
            }
        }
    }

    // ---- epilogue: ang = angular@Wa+ba (angular from gmem), mult, store ----
    const int gc = (lane & 3) * 2;
#pragma unroll
    for (int band = 0; band < 2; band++) {
        float (*ac)[4] = band ? acc1 : acc0;
#pragma unroll
        for (int rs = 0; rs < 2; rs++) {
            const int m = m0 + band * 16 + rs * 8 + r0;
            float sa[16];
            {
                const float4* ap = (const float4*)(angular + (size_t)(n0 + m) * ANG_F);
#pragma unroll
                for (int q4 = 0; q4 < 4; q4++) {
                    float4 v = __ldg(ap + q4);
                    sa[q4 * 4 + 0] = v.x; sa[q4 * 4 + 1] = v.y;
                    sa[q4 * 4 + 2] = v.z; sa[q4 * 4 + 3] = v.w;
                }
            }
            const size_t orow = (size_t)(n0 + m) * OUT_F;
#pragma unroll
            for (int nt = 0; nt < 4; nt++) {
                const int c0 = nc0 + nt * 8 + gc;
                float a0 = sba_[c0], a1 = sba_[c0 + 1];
#pragma unroll
                for (int q = 0; q < 16; q++) {
                    a0 = fmaf(sa[q], sWa[q * 64 + c0], a0);
                    a1 = fmaf(sa[q], sWa[q * 64 + c0 + 1], a1);
                }
                float2 o;
                o.x = ac[nt][rs * 2 + 0] * a0;
                o.y = ac[nt][rs * 2 + 1] * a1;
                *(float2*)(out + orow + c0) = o;
            }
        }
    }
}

// ---------------------------------------------------------------------------
// Launch
// ---------------------------------------------------------------------------
extern "C" void kernel_launch(void* const* d_in, const int* in_sizes, int n_in,
                              void* d_out, int out_size)
{
    const float* features = (const float*)d_in[0];
    const float* radial   = (const float*)d_in[1];
    const float* angular  = (const float*)d_in[2];
    const float* W1       = (const float*)d_in[3];
    const float* b1       = (const float*)d_in[4];
    const float* W2       = (const float*)d_in[5];
    const float* b2       = (const float*)d_in[6];
    const float* Wa       = (const float*)d_in[7];
    const float* ba       = (const float*)d_in[8];
    float* out = (float*)d_out;
    (void)in_sizes; (void)n_in; (void)out_size;

    cudaFuncSetAttribute(tp_main, cudaFuncAttributeMaxDynamicSharedMemorySize, SMEM_BYTES);

    tp_wsplit<<<(64 * 4096 + 4096 + THREADS - 1) / THREADS, THREADS>>>(W2, b2);
    tp_main<<<NTILES, THREADS, SMEM_BYTES>>>(features, radial, angular,
                                             W1, b1, Wa, ba, out);
}

// round 13
// speedup vs baseline: 1.2984x; 1.0794x over previous
#include <cuda_runtime.h>
#include <cuda_fp16.h>
#include <math.h>
#include <stdint.h>

#define NTOK  65536
#define IN_F  64
#define OUT_F 64
#define RAD_F 32
#define ANG_F 16
#define HID   64

#define TILE_M   128
#define NTILES   (NTOK / TILE_M)   // 512
#define THREADS  256

#define APITCH   144               // fp16 tile pitch (ldsm conflict-free)

// ---------------------------------------------------------------------------
// B stream in FRAGMENT order:
// addr(slot, nh, ks, row16, lane, j, byte) =
//   (slot*2+nh)*4096 + (ks*2+row16)*512 + lane*16 + j*4 + byte*2
// One LDG.128 per (ks,row16) gives lane's bh[0..3] / bh[4..7].
// Slots 0..63 = W2_i, slot 64 = b2.
// ---------------------------------------------------------------------------
__device__ __align__(1024) uint8_t g_streamR[(size_t)66 * 8192];

__device__ __forceinline__ void store_frag(int slot, int o, int k, __half v) {
    const int nh    = o >> 5;
    const int ol    = o & 31;
    const int row16 = ol >> 4;
    const int oo    = ol & 15;
    const int ks    = k >> 4;
    const int kl    = k & 15;
    const int j     = (oo >> 3) * 2 + (kl >> 3);
    const int lane  = (oo & 7) * 4 + ((kl & 7) >> 1);
    const int byte  = kl & 1;
    const size_t addr = (size_t)(slot * 2 + nh) * 4096
                      + (size_t)(ks * 2 + row16) * 512
                      + (size_t)lane * 16 + j * 4 + byte * 2;
    *(__half*)(g_streamR + addr) = v;
}

__global__ void tp_wsplit(const float* __restrict__ W2, const float* __restrict__ b2)
{
    const int idx = blockIdx.x * THREADS + threadIdx.x;
    if (idx < 64 * 4096) {
        const int k  = idx >> 12;
        const int io = idx & 4095;
        const int o  = io & 63;
        const int i  = io >> 6;
        store_frag(i, o, k, __float2half_rn(W2[idx]));
    } else if (idx < 64 * 4096 + 4096) {
        const int e = idx - 64 * 4096;
        const int i = e >> 6;     // contraction dim of the b2 pass
        const int o = e & 63;
        store_frag(64, o, i, __float2half_rn(b2[e]));
    }
}

// ---------------------------------------------------------------------------
// PTX helpers
// ---------------------------------------------------------------------------
__device__ __forceinline__ void ldsm_x4(uint32_t* r, uint32_t addr) {
    asm volatile("ldmatrix.sync.aligned.m8n8.x4.shared.b16 {%0,%1,%2,%3}, [%4];"
        : "=r"(r[0]), "=r"(r[1]), "=r"(r[2]), "=r"(r[3]) : "r"(addr));
}
__device__ __forceinline__ void mma_f16(float* d, const uint32_t* a,
                                        uint32_t b0, uint32_t b1) {
    asm volatile(
        "mma.sync.aligned.m16n8k16.row.col.f32.f16.f16.f32 "
        "{%0,%1,%2,%3}, {%4,%5,%6,%7}, {%8,%9}, {%0,%1,%2,%3};"
        : "+f"(d[0]), "+f"(d[1]), "+f"(d[2]), "+f"(d[3])
        : "r"(a[0]), "r"(a[1]), "r"(a[2]), "r"(a[3]), "r"(b0), "r"(b1));
}
__device__ __forceinline__ uint32_t hmul2u(uint32_t a, uint32_t f) {
    uint32_t d;
    asm("mul.rn.f16x2 %0, %1, %2;" : "=r"(d) : "r"(a), "r"(f));
    return d;
}
__device__ __forceinline__ uint32_t lds32(uint32_t addr) {
    uint32_t v;
    asm volatile("ld.shared.b32 %0, [%1];" : "=r"(v) : "r"(addr));
    return v;
}
__device__ __forceinline__ float silu_tanh(float x) {
    float t;
    asm("tanh.approx.f32 %0, %1;" : "=f"(t) : "f"(0.5f * x));
    const float hx = 0.5f * x;
    return fmaf(hx, t, hx);
}

// ---------------------------------------------------------------------------
// SMEM layout (bytes) — 49664 total (A/F/weights only; B never touches smem)
// ---------------------------------------------------------------------------
#define SM_A    0u        // h fp16 tile 128 rows          (18432)
#define SM_F    18432u    // radial staging, then f fp16   (18432)
#define SM_W1   36864u    // W1 fp32 [32][64]              (8192)
#define SM_WA   45056u    // Wa fp32 [16][64]              (4096)
#define SM_B1   49152u    // b1 fp32 [64]                  (256)
#define SM_BA   49408u    // ba fp32 [64]                  (256)
#define SMEM_BYTES 49664

// ---------------------------------------------------------------------------
// Main kernel: 128 tokens/CTA, 8 warps, 2 CTAs/SM.
// Warp = (m-pair, n-half): 32 rows x 32 cols. B via LDG fragments;
// ZERO __syncthreads in the mainloop.
// ---------------------------------------------------------------------------
__global__ __launch_bounds__(THREADS, 2)
void tp_main(const float* __restrict__ features,
             const float* __restrict__ radial,
             const float* __restrict__ angular,
             const float* __restrict__ W1,
             const float* __restrict__ b1,
             const float* __restrict__ Wa,
             const float* __restrict__ ba,
             float* __restrict__ out)
{
    extern __shared__ __align__(1024) uint8_t smem[];
    const uint32_t sb = (uint32_t)__cvta_generic_to_shared(smem);
    const int tid  = threadIdx.x;
    const int lane = tid & 31;
    const int warp = tid >> 5;
    const int n0   = blockIdx.x * TILE_M;

    // ---- stage radial (into SM_F region) + weights ----
    float* srad = (float*)(smem + SM_F);     // [128][33]
    float* sW1  = (float*)(smem + SM_W1);
    float* sWa  = (float*)(smem + SM_WA);
    float* sb1_ = (float*)(smem + SM_B1);
    float* sba_ = (float*)(smem + SM_BA);

    for (int e = tid; e < TILE_M * RAD_F; e += THREADS) {
        const int m = e >> 5, r = e & 31;
        srad[m * 33 + r] = radial[(size_t)(n0 + m) * RAD_F + r];
    }
    for (int e = tid; e < RAD_F * HID; e += THREADS) sW1[e] = W1[e];
    for (int e = tid; e < ANG_F * OUT_F; e += THREADS) sWa[e] = Wa[e];
    if (tid < HID)   sb1_[tid] = b1[tid];
    else if (tid < HID + OUT_F) sba_[tid - HID] = ba[tid - HID];
    __syncthreads();

    // ---- h = silu(radial@W1+b1) -> A tile (fp16) ----
    {
        const int j  = tid & 63;
        const int mb = tid >> 6;
#pragma unroll 4
        for (int s = 0; s < TILE_M / 4; s++) {
            const int m = mb + s * 4;
            float a = sb1_[j];
#pragma unroll
            for (int r = 0; r < RAD_F; r++)
                a = fmaf(srad[m * 33 + r], sW1[r * HID + j], a);
            *(__half*)(smem + SM_A + m * APITCH + j * 2) =
                __float2half_rn(silu_tanh(a));
        }
    }
    __syncthreads();   // A complete; radial fully consumed

    // ---- warp decomposition (validated R9-R12) ----
    const int mpair = warp >> 1;
    const int nhalf = warp & 1;
    const int m0    = mpair * 32;
    const int nc0   = nhalf * 32;

    const uint32_t a_row  = ((lane >> 3) & 1) * 8 + (lane & 7);
    const uint32_t a_kadd = (lane >> 4) * 16;
    const int r0 = lane >> 2;

    // ---- load A (h) fragments; write f fp16 tile over radial ----
    uint32_t Ah0[4][4], Ah1[4][4];
    {
        const uint32_t base0 = sb + SM_A + (m0 + a_row) * APITCH + a_kadd;
        const uint32_t base1 = base0 + 16 * APITCH;
#pragma unroll
        for (int ks = 0; ks < 4; ks++) ldsm_x4(Ah0[ks], base0 + ks * 32);
#pragma unroll
        for (int ks = 0; ks < 4; ks++) ldsm_x4(Ah1[ks], base1 + ks * 32);
    }
    for (int e = tid; e < TILE_M * IN_F; e += THREADS) {
        const int m = e >> 6, c = e & 63;
        const float v = features[(size_t)(n0 + m) * IN_F + c];
        *(__half*)(smem + SM_F + m * APITCH + c * 2) = __float2half_rn(v);
    }
    __syncthreads();   // all warps have A frags; F tile visible

    float acc0[4][4], acc1[4][4];
#pragma unroll
    for (int nt = 0; nt < 4; nt++)
#pragma unroll
        for (int j = 0; j < 4; j++) { acc0[nt][j] = 0.0f; acc1[nt][j] = 0.0f; }

    const uint32_t fa0 = sb + SM_F + (m0 + r0) * APITCH;   // band0 row r0
    const uint32_t fa1 = fa0 + 8 * APITCH;
    const uint32_t fa2 = fa0 + 16 * APITCH;
    const uint32_t fa3 = fa0 + 24 * APITCH;

    // per-warp/lane base into the fragment stream
    const uint8_t* bw = g_streamR + (size_t)nhalf * 4096 + (uint32_t)lane * 16;

    // ---- mainloop: 64 slots, NO barriers, NO smem for B ----
    for (int jp = 0; jp < 32; jp++) {
        const uint32_t v0 = lds32(fa0 + jp * 4);
        const uint32_t v1 = lds32(fa1 + jp * 4);
        const uint32_t v2 = lds32(fa2 + jp * 4);
        const uint32_t v3 = lds32(fa3 + jp * 4);

#pragma unroll
        for (int half = 0; half < 2; half++) {
            const int i = jp * 2 + half;
            const uint8_t* sbase = bw + (size_t)i * 8192;

            const uint32_t sel = half ? 0x3232u : 0x1010u;
            const uint32_t f0 = __byte_perm(v0, v0, sel);
            const uint32_t f1 = __byte_perm(v1, v1, sel);
            const uint32_t f2 = __byte_perm(v2, v2, sel);
            const uint32_t f3 = __byte_perm(v3, v3, sel);

#pragma unroll
            for (int ks = 0; ks < 4; ks++) {
                const uint4 bA = __ldg((const uint4*)(sbase + (ks * 2 + 0) * 512));
                const uint4 bB = __ldg((const uint4*)(sbase + (ks * 2 + 1) * 512));

                // A frag regs {0,2} = row r0, {1,3} = row r0+8
                uint32_t As0[4], As1[4];
                As0[0] = hmul2u(Ah0[ks][0], f0);
                As0[1] = hmul2u(Ah0[ks][1], f1);
                As0[2] = hmul2u(Ah0[ks][2], f0);
                As0[3] = hmul2u(Ah0[ks][3], f1);
                As1[0] = hmul2u(Ah1[ks][0], f2);
                As1[1] = hmul2u(Ah1[ks][1], f3);
                As1[2] = hmul2u(Ah1[ks][2], f2);
                As1[3] = hmul2u(Ah1[ks][3], f3);

                mma_f16(acc0[0], As0, bA.x, bA.y);
                mma_f16(acc1[0], As1, bA.x, bA.y);
                mma_f16(acc0[1], As0, bA.z, bA.w);
                mma_f16(acc1[1], As1, bA.z, bA.w);
                mma_f16(acc0[2], As0, bB.x, bB.y);
                mma_f16(acc1[2], As1, bB.x, bB.y);
                mma_f16(acc0[3], As0, bB.z, bB.w);
                mma_f16(acc1[3], As1, bB.z, bB.w);
            }
        }
    }

    // ---- b2 pass: slot 64, A = unscaled f fragments ----
    {
        uint32_t Fh0[4], Fh1[4];
        const uint32_t base0 = sb + SM_F + (m0 + a_row) * APITCH + a_kadd;
        const uint32_t base1 = base0 + 16 * APITCH;
        const uint8_t* sbase = bw + (size_t)64 * 8192;
#pragma unroll
        for (int ks = 0; ks < 4; ks++) {
            ldsm_x4(Fh0, base0 + ks * 32);
            ldsm_x4(Fh1, base1 + ks * 32);
            const uint4 bA = __ldg((const uint4*)(sbase + (ks * 2 + 0) * 512));
            const uint4 bB = __ldg((const uint4*)(sbase + (ks * 2 + 1) * 512));
            mma_f16(acc0[0], Fh0, bA.x, bA.y);
            mma_f16(acc1[0], Fh1, bA.x, bA.y);
            mma_f16(acc0[1], Fh0, bA.z, bA.w);
            mma_f16(acc1[1], Fh1, bA.z, bA.w);
            mma_f16(acc0[2], Fh0, bB.x, bB.y);
            mma_f16(acc1[2], Fh1, bB.x, bB.y);
            mma_f16(acc0[3], Fh0, bB.z, bB.w);
            mma_f16(acc1[3], Fh1, bB.z, bB.w);
        }
    }

    // ---- epilogue: ang = angular@Wa+ba (angular from gmem), mult, store ----
    const int gc = (lane & 3) * 2;
#pragma unroll
    for (int band = 0; band < 2; band++) {
        float (*ac)[4] = band ? acc1 : acc0;
#pragma unroll
        for (int rs = 0; rs < 2; rs++) {
            const int m = m0 + band * 16 + rs * 8 + r0;
            float sa[16];
            {
                const float4* ap = (const float4*)(angular + (size_t)(n0 + m) * ANG_F);
#pragma unroll
                for (int q4 = 0; q4 < 4; q4++) {
                    float4 v = __ldg(ap + q4);
                    sa[q4 * 4 + 0] = v.x; sa[q4 * 4 + 1] = v.y;
                    sa[q4 * 4 + 2] = v.z; sa[q4 * 4 + 3] = v.w;
                }
            }
            const size_t orow = (size_t)(n0 + m) * OUT_F;
#pragma unroll
            for (int nt = 0; nt < 4; nt++) {
                const int c0 = nc0 + nt * 8 + gc;
                float a0 = sba_[c0], a1 = sba_[c0 + 1];
#pragma unroll
                for (int q = 0; q < 16; q++) {
                    a0 = fmaf(sa[q], sWa[q * 64 + c0], a0);
                    a1 = fmaf(sa[q], sWa[q * 64 + c0 + 1], a1);
                }
                float2 o;
                o.x = ac[nt][rs * 2 + 0] * a0;
                o.y = ac[nt][rs * 2 + 1] * a1;
                *(float2*)(out + orow + c0) = o;
            }
        }
    }
}

// ---------------------------------------------------------------------------
// Launch
// ---------------------------------------------------------------------------
extern "C" void kernel_launch(void* const* d_in, const int* in_sizes, int n_in,
                              void* d_out, int out_size)
{
    const float* features = (const float*)d_in[0];
    const float* radial   = (const float*)d_in[1];
    const float* angular  = (const float*)d_in[2];
    const float* W1       = (const float*)d_in[3];
    const float* b1       = (const float*)d_in[4];
    const float* W2       = (const float*)d_in[5];
    const float* b2       = (const float*)d_in[6];
    const float* Wa       = (const float*)d_in[7];
    const float* ba       = (const float*)d_in[8];
    float* out = (float*)d_out;
    (void)in_sizes; (void)n_in; (void)out_size;

    cudaFuncSetAttribute(tp_main, cudaFuncAttributeMaxDynamicSharedMemorySize, SMEM_BYTES);

    tp_wsplit<<<(64 * 4096 + 4096 + THREADS - 1) / THREADS, THREADS>>>(W2, b2);
    tp_main<<<NTILES, THREADS, SMEM_BYTES>>>(features, radial, angular,
                                             W1, b1, Wa, ba, out);
}

// round 14
// speedup vs baseline: 1.3201x; 1.0167x over previous
#include <cuda_runtime.h>
#include <cuda_fp16.h>
#include <math.h>
#include <stdint.h>

#define NTOK  65536
#define IN_F  64
#define OUT_F 64
#define RAD_F 32
#define ANG_F 16
#define HID   64

#define TILE_M   128
#define NTILES   (NTOK / TILE_M)   // 512
#define THREADS  256

#define APITCH   144               // fp16 tile pitch (ldsm conflict-free)

// ---------------------------------------------------------------------------
// B stream in FRAGMENT order (validated R13):
// addr(slot, nh, ks, row16, lane, j, byte) =
//   (slot*2+nh)*4096 + (ks*2+row16)*512 + lane*16 + j*4 + byte*2
// Slots 0..63 = W2_i, slot 64 = b2.  For fixed nh: slot stride 8192,
// ks stride 1024 -> slot 64 is contiguous after slot 63 (prefetch-friendly).
// ---------------------------------------------------------------------------
__device__ __align__(1024) uint8_t g_streamR[(size_t)66 * 8192];

__device__ __forceinline__ void store_frag(int slot, int o, int k, __half v) {
    const int nh    = o >> 5;
    const int ol    = o & 31;
    const int row16 = ol >> 4;
    const int oo    = ol & 15;
    const int ks    = k >> 4;
    const int kl    = k & 15;
    const int j     = (oo >> 3) * 2 + (kl >> 3);
    const int lane  = (oo & 7) * 4 + ((kl & 7) >> 1);
    const int byte  = kl & 1;
    const size_t addr = (size_t)(slot * 2 + nh) * 4096
                      + (size_t)(ks * 2 + row16) * 512
                      + (size_t)lane * 16 + j * 4 + byte * 2;
    *(__half*)(g_streamR + addr) = v;
}

__global__ void tp_wsplit(const float* __restrict__ W2, const float* __restrict__ b2)
{
    const int idx = blockIdx.x * THREADS + threadIdx.x;
    if (idx < 64 * 4096) {
        const int k  = idx >> 12;
        const int io = idx & 4095;
        const int o  = io & 63;
        const int i  = io >> 6;
        store_frag(i, o, k, __float2half_rn(W2[idx]));
    } else if (idx < 64 * 4096 + 4096) {
        const int e = idx - 64 * 4096;
        const int i = e >> 6;     // contraction dim of the b2 pass
        const int o = e & 63;
        store_frag(64, o, i, __float2half_rn(b2[e]));
    }
}

// ---------------------------------------------------------------------------
// PTX helpers
// ---------------------------------------------------------------------------
__device__ __forceinline__ void ldsm_x4(uint32_t* r, uint32_t addr) {
    asm volatile("ldmatrix.sync.aligned.m8n8.x4.shared.b16 {%0,%1,%2,%3}, [%4];"
        : "=r"(r[0]), "=r"(r[1]), "=r"(r[2]), "=r"(r[3]) : "r"(addr));
}
__device__ __forceinline__ void mma_f16(float* d, const uint32_t* a,
                                        uint32_t b0, uint32_t b1) {
    asm volatile(
        "mma.sync.aligned.m16n8k16.row.col.f32.f16.f16.f32 "
        "{%0,%1,%2,%3}, {%4,%5,%6,%7}, {%8,%9}, {%0,%1,%2,%3};"
        : "+f"(d[0]), "+f"(d[1]), "+f"(d[2]), "+f"(d[3])
        : "r"(a[0]), "r"(a[1]), "r"(a[2]), "r"(a[3]), "r"(b0), "r"(b1));
}
__device__ __forceinline__ uint32_t hmul2u(uint32_t a, uint32_t f) {
    uint32_t d;
    asm("mul.rn.f16x2 %0, %1, %2;" : "=r"(d) : "r"(a), "r"(f));
    return d;
}
__device__ __forceinline__ uint32_t lds32(uint32_t addr) {
    uint32_t v;
    asm volatile("ld.shared.b32 %0, [%1];" : "=r"(v) : "r"(addr));
    return v;
}
__device__ __forceinline__ float silu_tanh(float x) {
    float t;
    asm("tanh.approx.f32 %0, %1;" : "=f"(t) : "f"(0.5f * x));
    const float hx = 0.5f * x;
    return fmaf(hx, t, hx);
}

// ---------------------------------------------------------------------------
// SMEM layout (bytes) — 49664 total
// ---------------------------------------------------------------------------
#define SM_A    0u        // h fp16 tile 128 rows          (18432)
#define SM_F    18432u    // radial staging, then f fp16   (18432)
#define SM_W1   36864u    // W1 fp32 [32][64]              (8192)
#define SM_WA   45056u    // Wa fp32 [16][64]              (4096)
#define SM_B1   49152u    // b1 fp32 [64]                  (256)
#define SM_BA   49408u    // ba fp32 [64]                  (256)
#define SMEM_BYTES 49664

// ---------------------------------------------------------------------------
// Main kernel: 128 tokens/CTA, 8 warps, 2 CTAs/SM.
// Warp = (m-pair, n-half): 32 rows x 32 cols. B via LDG fragments with
// distance-1 software prefetch; ZERO mainloop barriers.
// ---------------------------------------------------------------------------
__global__ __launch_bounds__(THREADS, 2)
void tp_main(const float* __restrict__ features,
             const float* __restrict__ radial,
             const float* __restrict__ angular,
             const float* __restrict__ W1,
             const float* __restrict__ b1,
             const float* __restrict__ Wa,
             const float* __restrict__ ba,
             float* __restrict__ out)
{
    extern __shared__ __align__(1024) uint8_t smem[];
    const uint32_t sb = (uint32_t)__cvta_generic_to_shared(smem);
    const int tid  = threadIdx.x;
    const int lane = tid & 31;
    const int warp = tid >> 5;
    const int n0   = blockIdx.x * TILE_M;

    // ---- stage radial (into SM_F region) + weights ----
    float* srad = (float*)(smem + SM_F);     // [128][33]
    float* sW1  = (float*)(smem + SM_W1);
    float* sWa  = (float*)(smem + SM_WA);
    float* sb1_ = (float*)(smem + SM_B1);
    float* sba_ = (float*)(smem + SM_BA);

    for (int e = tid; e < TILE_M * RAD_F; e += THREADS) {
        const int m = e >> 5, r = e & 31;
        srad[m * 33 + r] = radial[(size_t)(n0 + m) * RAD_F + r];
    }
    for (int e = tid; e < RAD_F * HID; e += THREADS) sW1[e] = W1[e];
    for (int e = tid; e < ANG_F * OUT_F; e += THREADS) sWa[e] = Wa[e];
    if (tid < HID)   sb1_[tid] = b1[tid];
    else if (tid < HID + OUT_F) sba_[tid - HID] = ba[tid - HID];
    __syncthreads();

    // ---- h = silu(radial@W1+b1) -> A tile (fp16) ----
    {
        const int j  = tid & 63;
        const int mb = tid >> 6;
#pragma unroll 4
        for (int s = 0; s < TILE_M / 4; s++) {
            const int m = mb + s * 4;
            float a = sb1_[j];
#pragma unroll
            for (int r = 0; r < RAD_F; r++)
                a = fmaf(srad[m * 33 + r], sW1[r * HID + j], a);
            *(__half*)(smem + SM_A + m * APITCH + j * 2) =
                __float2half_rn(silu_tanh(a));
        }
    }
    __syncthreads();   // A complete; radial fully consumed

    // ---- warp decomposition (validated R9-R13) ----
    const int mpair = warp >> 1;
    const int nhalf = warp & 1;
    const int m0    = mpair * 32;
    const int nc0   = nhalf * 32;

    const uint32_t a_row  = ((lane >> 3) & 1) * 8 + (lane & 7);
    const uint32_t a_kadd = (lane >> 4) * 16;
    const int r0 = lane >> 2;

    // ---- load A (h) fragments; write f fp16 tile over radial ----
    uint32_t Ah0[4][4], Ah1[4][4];
    {
        const uint32_t base0 = sb + SM_A + (m0 + a_row) * APITCH + a_kadd;
        const uint32_t base1 = base0 + 16 * APITCH;
#pragma unroll
        for (int ks = 0; ks < 4; ks++) ldsm_x4(Ah0[ks], base0 + ks * 32);
#pragma unroll
        for (int ks = 0; ks < 4; ks++) ldsm_x4(Ah1[ks], base1 + ks * 32);
    }
    for (int e = tid; e < TILE_M * IN_F; e += THREADS) {
        const int m = e >> 6, c = e & 63;
        const float v = features[(size_t)(n0 + m) * IN_F + c];
        *(__half*)(smem + SM_F + m * APITCH + c * 2) = __float2half_rn(v);
    }
    __syncthreads();   // all warps have A frags; F tile visible

    float acc0[4][4], acc1[4][4];
#pragma unroll
    for (int nt = 0; nt < 4; nt++)
#pragma unroll
        for (int j = 0; j < 4; j++) { acc0[nt][j] = 0.0f; acc1[nt][j] = 0.0f; }

    const uint32_t fa0 = sb + SM_F + (m0 + r0) * APITCH;   // band0 row r0
    const uint32_t fa1 = fa0 + 8 * APITCH;
    const uint32_t fa2 = fa0 + 16 * APITCH;
    const uint32_t fa3 = fa0 + 24 * APITCH;

    // per-warp/lane base into the fragment stream
    const uint8_t* bw = g_streamR + (size_t)nhalf * 4096 + (uint32_t)lane * 16;

    // prime the pipeline: slot 0, ks 0
    uint4 cA = __ldg((const uint4*)(bw));
    uint4 cB = __ldg((const uint4*)(bw + 512));

    // ---- mainloop: 64 slots; distance-1 prefetch; NO barriers ----
    for (int jp = 0; jp < 32; jp++) {
        const uint32_t v0 = lds32(fa0 + jp * 4);
        const uint32_t v1 = lds32(fa1 + jp * 4);
        const uint32_t v2 = lds32(fa2 + jp * 4);
        const uint32_t v3 = lds32(fa3 + jp * 4);

#pragma unroll
        for (int half = 0; half < 2; half++) {
            const int i = jp * 2 + half;
            const uint8_t* sbase = bw + (size_t)i * 8192;

            const uint32_t sel = half ? 0x3232u : 0x1010u;
            const uint32_t f0 = __byte_perm(v0, v0, sel);
            const uint32_t f1 = __byte_perm(v1, v1, sel);
            const uint32_t f2 = __byte_perm(v2, v2, sel);
            const uint32_t f3 = __byte_perm(v3, v3, sel);

#pragma unroll
            for (int ks = 0; ks < 4; ks++) {
                // prefetch next ks-step (next slot at ks==3; slot 64 = b2
                // is contiguous after slot 63, so the final prefetch primes
                // the bias pass)
                const uint8_t* nbase = (ks < 3) ? (sbase + (ks + 1) * 1024)
                                                : (sbase + 8192);
                const uint4 nA = __ldg((const uint4*)(nbase));
                const uint4 nB = __ldg((const uint4*)(nbase + 512));

                // A frag regs {0,2} = row r0, {1,3} = row r0+8
                uint32_t As0[4], As1[4];
                As0[0] = hmul2u(Ah0[ks][0], f0);
                As0[1] = hmul2u(Ah0[ks][1], f1);
                As0[2] = hmul2u(Ah0[ks][2], f0);
                As0[3] = hmul2u(Ah0[ks][3], f1);
                As1[0] = hmul2u(Ah1[ks][0], f2);
                As1[1] = hmul2u(Ah1[ks][1], f3);
                As1[2] = hmul2u(Ah1[ks][2], f2);
                As1[3] = hmul2u(Ah1[ks][3], f3);

                mma_f16(acc0[0], As0, cA.x, cA.y);
                mma_f16(acc1[0], As1, cA.x, cA.y);
                mma_f16(acc0[1], As0, cA.z, cA.w);
                mma_f16(acc1[1], As1, cA.z, cA.w);
                mma_f16(acc0[2], As0, cB.x, cB.y);
                mma_f16(acc1[2], As1, cB.x, cB.y);
                mma_f16(acc0[3], As0, cB.z, cB.w);
                mma_f16(acc1[3], As1, cB.z, cB.w);

                cA = nA; cB = nB;
            }
        }
    }

    // ---- b2 pass: slot 64 (cA/cB already hold ks=0 via prefetch) ----
    {
        uint32_t Fh0[4], Fh1[4];
        const uint32_t base0 = sb + SM_F + (m0 + a_row) * APITCH + a_kadd;
        const uint32_t base1 = base0 + 16 * APITCH;
        const uint8_t* sbase = bw + (size_t)64 * 8192;
#pragma unroll
        for (int ks = 0; ks < 4; ks++) {
            uint4 nA, nB;
            if (ks < 3) {
                nA = __ldg((const uint4*)(sbase + (ks + 1) * 1024));
                nB = __ldg((const uint4*)(sbase + (ks + 1) * 1024 + 512));
            } else {
                nA = cA; nB = cB;
            }
            ldsm_x4(Fh0, base0 + ks * 32);
            ldsm_x4(Fh1, base1 + ks * 32);
            mma_f16(acc0[0], Fh0, cA.x, cA.y);
            mma_f16(acc1[0], Fh1, cA.x, cA.y);
            mma_f16(acc0[1], Fh0, cA.z, cA.w);
            mma_f16(acc1[1], Fh1, cA.z, cA.w);
            mma_f16(acc0[2], Fh0, cB.x, cB.y);
            mma_f16(acc1[2], Fh1, cB.x, cB.y);
            mma_f16(acc0[3], Fh0, cB.z, cB.w);
            mma_f16(acc1[3], Fh1, cB.z, cB.w);
            cA = nA; cB = nB;
        }
    }

    // ---- epilogue: ang = angular@Wa+ba (angular from gmem), mult, store ----
    const int gc = (lane & 3) * 2;
#pragma unroll
    for (int band = 0; band < 2; band++) {
        float (*ac)[4] = band ? acc1 : acc0;
#pragma unroll
        for (int rs = 0; rs < 2; rs++) {
            const int m = m0 + band * 16 + rs * 8 + r0;
            float sa[16];
            {
                const float4* ap = (const float4*)(angular + (size_t)(n0 + m) * ANG_F);
#pragma unroll
                for (int q4 = 0; q4 < 4; q4++) {
                    float4 v = __ldg(ap + q4);
                    sa[q4 * 4 + 0] = v.x; sa[q4 * 4 + 1] = v.y;
                    sa[q4 * 4 + 2] = v.z; sa[q4 * 4 + 3] = v.w;
                }
            }
            const size_t orow = (size_t)(n0 + m) * OUT_F;
#pragma unroll
            for (int nt = 0; nt < 4; nt++) {
                const int c0 = nc0 + nt * 8 + gc;
                float a0 = sba_[c0], a1 = sba_[c0 + 1];
#pragma unroll
                for (int q = 0; q < 16; q++) {
                    a0 = fmaf(sa[q], sWa[q * 64 + c0], a0);
                    a1 = fmaf(sa[q], sWa[q * 64 + c0 + 1], a1);
                }
                float2 o;
                o.x = ac[nt][rs * 2 + 0] * a0;
                o.y = ac[nt][rs * 2 + 1] * a1;
                *(float2*)(out + orow + c0) = o;
            }
        }
    }
}

// ---------------------------------------------------------------------------
// Launch
// ---------------------------------------------------------------------------
extern "C" void kernel_launch(void* const* d_in, const int* in_sizes, int n_in,
                              void* d_out, int out_size)
{
    const float* features = (const float*)d_in[0];
    const float* radial   = (const float*)d_in[1];
    const float* angular  = (const float*)d_in[2];
    const float* W1       = (const float*)d_in[3];
    const float* b1       = (const float*)d_in[4];
    const float* W2       = (const float*)d_in[5];
    const float* b2       = (const float*)d_in[6];
    const float* Wa       = (const float*)d_in[7];
    const float* ba       = (const float*)d_in[8];
    float* out = (float*)d_out;
    (void)in_sizes; (void)n_in; (void)out_size;

    cudaFuncSetAttribute(tp_main, cudaFuncAttributeMaxDynamicSharedMemorySize, SMEM_BYTES);

    tp_wsplit<<<(64 * 4096 + 4096 + THREADS - 1) / THREADS, THREADS>>>(W2, b2);
    tp_main<<<NTILES, THREADS, SMEM_BYTES>>>(features, radial, angular,
                                             W1, b1, Wa, ba, out);
}